// round 15
// baseline (speedup 1.0000x reference)
#include <cuda_runtime.h>
#include <cuda_bf16.h>
#include <cstdint>
#include <cstddef>

// Problem constants: B=4, T=2048, C=2048, H=16, G=4, HKV=4, D=128, KV=512
#define AT_B   4
#define AT_T   2048
#define AT_C   2048
#define AT_KV  512
#define AT_D   128
#define AT_H   16
#define AT_HKV 4
#define AT_SCALE 0.08838834764831845f  // 1/sqrt(128)

typedef unsigned long long u64;
typedef unsigned int u32;

// ---------------------------------------------------------------------------
// Common helpers
// ---------------------------------------------------------------------------
__device__ __forceinline__ void pack2hl(float x, float y, u32& h, u32& l) {
    __nv_bfloat162 hv = __float22bfloat162_rn(make_float2(x, y));
    float lx = x - __low2float(hv), ly = y - __high2float(hv);
    __nv_bfloat162 lv = __float22bfloat162_rn(make_float2(lx, ly));
    h = *reinterpret_cast<u32*>(&hv);
    l = *reinterpret_cast<u32*>(&lv);
}

// ---- legacy mma helpers (proven R8-R14) ----
__device__ __forceinline__ void ldsm4(u32* r, u32 addr) {
    asm volatile("ldmatrix.sync.aligned.m8n8.x4.shared.b16 {%0,%1,%2,%3}, [%4];"
                 : "=r"(r[0]), "=r"(r[1]), "=r"(r[2]), "=r"(r[3]) : "r"(addr));
}
__device__ __forceinline__ void ldsm4t(u32* r, u32 addr) {
    asm volatile("ldmatrix.sync.aligned.m8n8.x4.trans.shared.b16 {%0,%1,%2,%3}, [%4];"
                 : "=r"(r[0]), "=r"(r[1]), "=r"(r[2]), "=r"(r[3]) : "r"(addr));
}
__device__ __forceinline__ void mma_bf16(float* d, const u32* a, u32 b0, u32 b1) {
    asm volatile("mma.sync.aligned.m16n8k16.row.col.f32.bf16.bf16.f32 "
                 "{%0,%1,%2,%3}, {%4,%5,%6,%7}, {%8,%9}, {%0,%1,%2,%3};"
                 : "+f"(d[0]), "+f"(d[1]), "+f"(d[2]), "+f"(d[3])
                 : "r"(a[0]), "r"(a[1]), "r"(a[2]), "r"(a[3]), "r"(b0), "r"(b1));
}

// ---- cp.async helpers ----
__device__ __forceinline__ void cpa16(u32 s, const void* g) {
    asm volatile("cp.async.cg.shared.global [%0], [%1], 16;" :: "r"(s), "l"(g) : "memory");
}
#define CP_COMMIT() asm volatile("cp.async.commit_group;" ::: "memory")
#define CP_WAIT(n)  asm volatile("cp.async.wait_group %0;" :: "n"(n) : "memory")

// ---------------------------------------------------------------------------
// Scratch (allocation-free rule: __device__ globals)
// ---------------------------------------------------------------------------
__device__ __nv_bfloat16 g_qh[AT_B * AT_T * AT_C], g_ql[AT_B * AT_T * AT_C];
__device__ __nv_bfloat16 g_kh[AT_B * AT_T * AT_C], g_kl[AT_B * AT_T * AT_C];
__device__ __nv_bfloat16 g_vh[AT_B * AT_T * AT_C], g_vl[AT_B * AT_T * AT_C];
__device__ __nv_bfloat16 g_wih[(AT_C + 2 * AT_KV) * AT_C], g_wil[(AT_C + 2 * AT_KV) * AT_C];
__device__ __nv_bfloat16 g_woh[AT_C * AT_C], g_wol[AT_C * AT_C];
__device__ __nv_bfloat16 g_xqh[AT_B * AT_T * AT_C],  g_xql[AT_B * AT_T * AT_C];
__device__ __nv_bfloat16 g_xkh[AT_B * AT_T * AT_KV], g_xkl[AT_B * AT_T * AT_KV];
__device__ __nv_bfloat16 g_xvh[AT_B * AT_T * AT_KV], g_xvl[AT_B * AT_T * AT_KV];
__device__ __nv_bfloat16 g_xoh[AT_B * AT_T * AT_C], g_xol[AT_B * AT_T * AT_C];

// ---------------------------------------------------------------------------
// Fused fp32 -> (bf16 hi, bf16 lo) split over all 5 tensors (one launch)
// ---------------------------------------------------------------------------
#define N_ACT (AT_B * AT_T * AT_C / 4)
#define N_IPW ((AT_C + 2 * AT_KV) * AT_C / 4)
#define N_OPW (AT_C * AT_C / 4)

__global__ void split_all_kernel(const float4* __restrict__ q, const float4* __restrict__ k,
                                 const float4* __restrict__ v, const float4* __restrict__ ipw,
                                 const float4* __restrict__ opw,
                                 uint2* qh, uint2* ql, uint2* kh, uint2* kl,
                                 uint2* vh, uint2* vl, uint2* wih, uint2* wil,
                                 uint2* woh, uint2* wol)
{
    const int total = 3 * N_ACT + N_IPW + N_OPW;
    for (int i = blockIdx.x * blockDim.x + threadIdx.x; i < total; i += gridDim.x * blockDim.x) {
        const float4* src; uint2 *hi, *lo; int j = i;
        if (j < N_ACT)                    { src = q;   hi = qh;  lo = ql;  }
        else if ((j -= N_ACT) < N_ACT)    { src = k;   hi = kh;  lo = kl;  }
        else if ((j -= N_ACT) < N_ACT)    { src = v;   hi = vh;  lo = vl;  }
        else if ((j -= N_ACT) < N_IPW)    { src = ipw; hi = wih; lo = wil; }
        else { j -= N_IPW;                  src = opw; hi = woh; lo = wol; }
        float4 val = src[j];
        u32 h0, l0, h1, l1;
        pack2hl(val.x, val.y, h0, l0);
        pack2hl(val.z, val.w, h1, l1);
        hi[j] = make_uint2(h0, h1);
        lo[j] = make_uint2(l0, l1);
    }
}

// ---------------------------------------------------------------------------
// bf16x3 HMMA GEMM core. R15: per-mf pass-major inner loop with a 2-deep
// A-fragment double buffer (al/ah) — removes the WAR ldsm stalls of the
// single-array reuse while keeping the same register count (occ 2).
// Loads for stage kt+3 are issued at the TOP of iteration kt (slot freed by
// the barrier just passed) for +1 iteration of prefetch cover.
// ---------------------------------------------------------------------------
#define STAGE_B 24576u

template<bool SPLIT>
__device__ __forceinline__
void gemm_core(const __nv_bfloat16* __restrict__ Ahi, const __nv_bfloat16* __restrict__ Alo,
               const __nv_bfloat16* __restrict__ Whi, const __nv_bfloat16* __restrict__ Wlo,
               const float* __restrict__ bias, float* __restrict__ out,
               __nv_bfloat16* __restrict__ oh, __nv_bfloat16* __restrict__ ol,
               int N, int K, int m0, int n0, float scl)
{
    extern __shared__ __align__(16) char dsm[];
    const u32 sb  = (u32)__cvta_generic_to_shared(dsm);
    const int tid = threadIdx.x;

    auto load_stage = [&](int kt) {
        const u32 base = sb + (u32)(kt & 3) * STAGE_B;
        const int kofs = kt * 16;
        #pragma unroll
        for (int t = 0; t < 2; t++) {
            int j = tid + t * 256;
            int arr = j >> 8, r = (j >> 1) & 127, c = j & 1;
            const __nv_bfloat16* gp = (arr ? Alo : Ahi) + (size_t)(m0 + r) * K + kofs + c * 8;
            cpa16(base + arr * 6144 + r * 48 + c * 16, gp);
        }
        #pragma unroll
        for (int t = 0; t < 2; t++) {
            int j = tid + t * 256;
            int arr = j >> 8, r = (j >> 1) & 127, c = j & 1;
            const __nv_bfloat16* gp = (arr ? Wlo : Whi) + (size_t)(n0 + r) * K + kofs + c * 8;
            cpa16(base + 12288 + arr * 6144 + r * 48 + c * 16, gp);
        }
        CP_COMMIT();
    };

    load_stage(0);
    load_stage(1);
    load_stage(2);

    const int wid  = tid >> 5, lane = tid & 31;
    const int wm   = (wid & 1) << 6;
    const int wn   = (wid >> 1) << 5;

    const u32 a_off = (u32)((wm + (lane & 7) + ((lane >> 3) & 1) * 8) * 48 + (lane >> 4) * 16);
    const u32 b_off = (u32)((wn + (lane & 7) + (lane >> 4) * 8) * 48 + ((lane >> 3) & 1) * 16);

    float acc[4][4][4] = {};

    const int nk = K >> 4;
    for (int kt = 0; kt < nk; kt++) {
        if (kt + 3 < nk) { CP_WAIT(2); } else { CP_WAIT(0); }
        __syncthreads();
        if (kt + 3 < nk) load_stage(kt + 3);   // slot (kt-1)&3, freed by barrier

        const u32 base = sb + (u32)(kt & 3) * STAGE_B;
        u32 bh[2][4], bl[2][4], al[2][4], ah[2][4];

        // B fragments (hi + lo) up front
        #pragma unroll
        for (int pf = 0; pf < 2; pf++) {
            ldsm4(bh[pf], base + 12288 + b_off + pf * 768);
            ldsm4(bl[pf], base + 18432 + b_off + pf * 768);
        }
        // First A fragments
        ldsm4(al[0], base + 6144 + a_off);
        ldsm4(ah[0], base + a_off);

        #pragma unroll
        for (int mf = 0; mf < 4; mf++) {
            const int cur = mf & 1, nxt = cur ^ 1;
            if (mf < 3) {   // prefetch next mf's A fragments under this mf's MMAs
                ldsm4(al[nxt], base + 6144 + a_off + (mf + 1) * 768);
                ldsm4(ah[nxt], base + a_off + (mf + 1) * 768);
            }
            #pragma unroll
            for (int nf = 0; nf < 4; nf++)
                mma_bf16(acc[mf][nf], al[cur], bh[nf >> 1][(nf & 1) * 2], bh[nf >> 1][(nf & 1) * 2 + 1]);
            #pragma unroll
            for (int nf = 0; nf < 4; nf++)
                mma_bf16(acc[mf][nf], ah[cur], bh[nf >> 1][(nf & 1) * 2], bh[nf >> 1][(nf & 1) * 2 + 1]);
            #pragma unroll
            for (int nf = 0; nf < 4; nf++)
                mma_bf16(acc[mf][nf], ah[cur], bl[nf >> 1][(nf & 1) * 2], bl[nf >> 1][(nf & 1) * 2 + 1]);
        }
    }

    const int gr  = lane >> 2;
    const int gc2 = (lane & 3) * 2;
    #pragma unroll
    for (int mf = 0; mf < 4; mf++) {
        int row0 = m0 + wm + mf * 16 + gr;
        #pragma unroll
        for (int nf = 0; nf < 4; nf++) {
            int col = n0 + wn + nf * 8 + gc2;
            float2 bv = *(const float2*)(bias + col);
            float v00 = (acc[mf][nf][0] + bv.x) * scl, v01 = (acc[mf][nf][1] + bv.y) * scl;
            float v10 = (acc[mf][nf][2] + bv.x) * scl, v11 = (acc[mf][nf][3] + bv.y) * scl;
            if (SPLIT) {
                u32 h0, l0, h1, l1;
                pack2hl(v00, v01, h0, l0);
                pack2hl(v10, v11, h1, l1);
                *(u32*)(oh + (size_t)row0 * N + col)       = h0;
                *(u32*)(ol + (size_t)row0 * N + col)       = l0;
                *(u32*)(oh + (size_t)(row0 + 8) * N + col) = h1;
                *(u32*)(ol + (size_t)(row0 + 8) * N + col) = l1;
            } else {
                *(float2*)(out + (size_t)row0 * N + col)       = make_float2(v00, v01);
                *(float2*)(out + (size_t)(row0 + 8) * N + col) = make_float2(v10, v11);
            }
        }
    }
}

// Merged Q+K+V projection: grid (24, 64).
//   bx in [0,16)  -> Q proj (N=2048), output pre-scaled by 1/sqrt(D)
//   bx in [16,20) -> K proj (N=512)
//   bx in [20,24) -> V proj (N=512)
__global__ __launch_bounds__(256, 2)
void gemm_mma_proj(const float* __restrict__ ipb)
{
    const int bx = blockIdx.x;
    const __nv_bfloat16 *Ahi, *Alo, *Whi, *Wlo;
    __nv_bfloat16 *oh, *ol;
    const float* bias;
    int N, n0;
    float scl;
    if (bx < 16) {
        Ahi = g_qh; Alo = g_ql; Whi = g_wih; Wlo = g_wil;
        bias = ipb; oh = g_xqh; ol = g_xql; N = AT_C; n0 = bx * 128; scl = AT_SCALE;
    } else if (bx < 20) {
        Ahi = g_kh; Alo = g_kl;
        Whi = g_wih + (size_t)AT_C * AT_C; Wlo = g_wil + (size_t)AT_C * AT_C;
        bias = ipb + AT_C; oh = g_xkh; ol = g_xkl; N = AT_KV; n0 = (bx - 16) * 128; scl = 1.0f;
    } else {
        Ahi = g_vh; Alo = g_vl;
        Whi = g_wih + (size_t)(AT_C + AT_KV) * AT_C; Wlo = g_wil + (size_t)(AT_C + AT_KV) * AT_C;
        bias = ipb + AT_C + AT_KV; oh = g_xvh; ol = g_xvl; N = AT_KV; n0 = (bx - 20) * 128; scl = 1.0f;
    }
    gemm_core<true>(Ahi, Alo, Whi, Wlo, bias, nullptr, oh, ol,
                    N, AT_C, blockIdx.y * 128, n0, scl);
}

// Output projection (fp32 out)
__global__ __launch_bounds__(256, 2)
void gemm_mma_out(const float* __restrict__ opb, float* __restrict__ out)
{
    gemm_core<false>(g_xoh, g_xol, g_woh, g_wol, opb, out, nullptr, nullptr,
                     AT_C, AT_C, blockIdx.y * 128, blockIdx.x * 128, 1.0f);
}

// ---------------------------------------------------------------------------
// Tensor-core flash attention (causal, GQA), bf16x3, BM=64, occ 2.
// Unchanged from R14 (Q pre-scaled + Q fragments hoisted).
// ---------------------------------------------------------------------------
__global__ __launch_bounds__(128, 2)
void attn_tc_kernel()
{
    extern __shared__ __align__(16) __nv_bfloat16 smx[];
    const u32 sb = (u32)__cvta_generic_to_shared(smx);
    const u32 QH = 0, QL = 17408, KH = 34816, KL = 52224, VH = 69632, VL = 87040;

    const int tid  = threadIdx.x;
    const int wid  = tid >> 5, lane = tid & 31;
    const int bx   = blockIdx.x;
    const int b    = bx >> 4;
    const int hd   = bx & 15;
    const int hkv  = hd & 3;
    const int qb   = 31 - blockIdx.y;          // heavy blocks first
    const int q0   = qb * 64;

    const __nv_bfloat16* qhp = g_xqh + ((size_t)b * AT_T + q0) * AT_C + hd * AT_D;
    const __nv_bfloat16* qlp = g_xql + ((size_t)b * AT_T + q0) * AT_C + hd * AT_D;
    const __nv_bfloat16* khp = g_xkh + (size_t)b * AT_T * AT_KV + hkv * AT_D;
    const __nv_bfloat16* klp = g_xkl + (size_t)b * AT_T * AT_KV + hkv * AT_D;
    const __nv_bfloat16* vhp = g_xvh + (size_t)b * AT_T * AT_KV + hkv * AT_D;
    const __nv_bfloat16* vlp = g_xvl + (size_t)b * AT_T * AT_KV + hkv * AT_D;

    auto load_K = [&](int j) {
        if (j <= qb) {
            for (int i = tid; i < 1024; i += 128) {
                int row = i >> 4, cc = (i & 15) << 3;
                size_t g = (size_t)(j * 64 + row) * AT_KV + cc;
                u32 so = row * 272 + cc * 2;
                cpa16(sb + KH + so, khp + g);
                cpa16(sb + KL + so, klp + g);
            }
        }
        CP_COMMIT();
    };
    auto load_V = [&](int j) {
        if (j <= qb) {
            for (int i = tid; i < 1024; i += 128) {
                int row = i >> 4, cc = (i & 15) << 3;
                size_t g = (size_t)(j * 64 + row) * AT_KV + cc;
                u32 so = row * 272 + cc * 2;
                cpa16(sb + VH + so, vhp + g);
                cpa16(sb + VL + so, vlp + g);
            }
        }
        CP_COMMIT();
    };

    // Q tile (64 x 128 halves, hi+lo)
    for (int i = tid; i < 1024; i += 128) {
        int row = i >> 4, cc = (i & 15) << 3;
        size_t g = (size_t)row * AT_C + cc;
        cpa16(sb + QH + row * 272 + cc * 2, qhp + g);
        cpa16(sb + QL + row * 272 + cc * 2, qlp + g);
    }
    CP_COMMIT();
    load_K(0);
    load_V(0);

    const int wq = wid * 16;
    const int gr = lane >> 2;
    const int qrow0 = q0 + wq + gr;
    const int qrow1 = qrow0 + 8;

    const u32 a_off = (u32)((wq + (lane & 7) + ((lane >> 3) & 1) * 8) * 272 + (lane >> 4) * 16);
    const u32 b_off = (u32)(((lane & 7) + (lane >> 4) * 8) * 272 + ((lane >> 3) & 1) * 16);
    const u32 v_off = (u32)(((lane & 7) + ((lane >> 3) & 1) * 8) * 272 + (lane >> 4) * 16);

    // Hoist Q fragments (tile-invariant) into registers
    u32 qah[8][4], qal[8][4];
    CP_WAIT(2);          // Q group complete (K0/V0 may be in flight)
    __syncthreads();
    #pragma unroll
    for (int c = 0; c < 8; c++) {
        ldsm4(qah[c], sb + QH + a_off + c * 32);
        ldsm4(qal[c], sb + QL + a_off + c * 32);
    }

    float o[16][4];
    #pragma unroll
    for (int nf = 0; nf < 16; nf++)
        #pragma unroll
        for (int k = 0; k < 4; k++) o[nf][k] = 0.f;
    float m0 = -1e30f, m1 = -1e30f, l0 = 0.f, l1 = 0.f;

    for (int j = 0; j <= qb; j++) {
        // K(j) complete; V(j) may still be in flight
        CP_WAIT(1);
        __syncthreads();

        // ---- S = Q K^T (bf16x3; Q from registers) ----
        float s[8][4];
        #pragma unroll
        for (int nf = 0; nf < 8; nf++)
            #pragma unroll
            for (int k = 0; k < 4; k++) s[nf][k] = 0.f;

        #pragma unroll
        for (int c = 0; c < 8; c++) {
            #pragma unroll
            for (int nb = 0; nb < 4; nb++) {
                u32 bh_[4], bl_[4];
                u32 ka = b_off + nb * 4352 + c * 32;
                ldsm4(bh_, sb + KH + ka);
                ldsm4(bl_, sb + KL + ka);
                mma_bf16(s[2 * nb],     qal[c], bh_[0], bh_[1]);
                mma_bf16(s[2 * nb + 1], qal[c], bh_[2], bh_[3]);
                mma_bf16(s[2 * nb],     qah[c], bl_[0], bl_[1]);
                mma_bf16(s[2 * nb + 1], qah[c], bl_[2], bl_[3]);
                mma_bf16(s[2 * nb],     qah[c], bh_[0], bh_[1]);
                mma_bf16(s[2 * nb + 1], qah[c], bh_[2], bh_[3]);
            }
        }

        __syncthreads();            // all warps done reading K(j)
        load_K(j + 1);              // hides under softmax + PV

        // ---- online softmax (Q pre-scaled; no scale muls) ----
        const bool maskt = (j == qb);
        const int colb = j * 64 + 2 * (lane & 3);
        float mx0 = -1e30f, mx1 = -1e30f;
        #pragma unroll
        for (int nf = 0; nf < 8; nf++) {
            int c0 = colb + 8 * nf;
            if (maskt) {
                if (c0     > qrow0) s[nf][0] = -1e30f;
                if (c0 + 1 > qrow0) s[nf][1] = -1e30f;
                if (c0     > qrow1) s[nf][2] = -1e30f;
                if (c0 + 1 > qrow1) s[nf][3] = -1e30f;
            }
            mx0 = fmaxf(mx0, fmaxf(s[nf][0], s[nf][1]));
            mx1 = fmaxf(mx1, fmaxf(s[nf][2], s[nf][3]));
        }
        mx0 = fmaxf(mx0, __shfl_xor_sync(0xffffffffu, mx0, 1));
        mx0 = fmaxf(mx0, __shfl_xor_sync(0xffffffffu, mx0, 2));
        mx1 = fmaxf(mx1, __shfl_xor_sync(0xffffffffu, mx1, 1));
        mx1 = fmaxf(mx1, __shfl_xor_sync(0xffffffffu, mx1, 2));

        float nm0 = fmaxf(m0, mx0), nm1 = fmaxf(m1, mx1);
        float corr0 = __expf(m0 - nm0), corr1 = __expf(m1 - nm1);
        m0 = nm0; m1 = nm1;

        float rs0 = 0.f, rs1 = 0.f;
        #pragma unroll
        for (int nf = 0; nf < 8; nf++) {
            s[nf][0] = __expf(s[nf][0] - m0); rs0 += s[nf][0];
            s[nf][1] = __expf(s[nf][1] - m0); rs0 += s[nf][1];
            s[nf][2] = __expf(s[nf][2] - m1); rs1 += s[nf][2];
            s[nf][3] = __expf(s[nf][3] - m1); rs1 += s[nf][3];
        }
        rs0 += __shfl_xor_sync(0xffffffffu, rs0, 1);
        rs0 += __shfl_xor_sync(0xffffffffu, rs0, 2);
        rs1 += __shfl_xor_sync(0xffffffffu, rs1, 1);
        rs1 += __shfl_xor_sync(0xffffffffu, rs1, 2);
        l0 = l0 * corr0 + rs0;
        l1 = l1 * corr1 + rs1;

        #pragma unroll
        for (int nf = 0; nf < 16; nf++) {
            o[nf][0] *= corr0; o[nf][1] *= corr0;
            o[nf][2] *= corr1; o[nf][3] *= corr1;
        }

        // V(j) complete (K(j+1) may still be in flight)
        CP_WAIT(1);
        __syncthreads();

        // ---- O += P V (bf16x3) ----
        #pragma unroll
        for (int c = 0; c < 4; c++) {
            u32 aph[4], apl[4];
            pack2hl(s[2 * c][0],     s[2 * c][1],     aph[0], apl[0]);
            pack2hl(s[2 * c][2],     s[2 * c][3],     aph[1], apl[1]);
            pack2hl(s[2 * c + 1][0], s[2 * c + 1][1], aph[2], apl[2]);
            pack2hl(s[2 * c + 1][2], s[2 * c + 1][3], aph[3], apl[3]);
            #pragma unroll
            for (int nb = 0; nb < 8; nb++) {
                u32 vh_[4], vl_[4];
                u32 va = v_off + c * 4352 + nb * 32;
                ldsm4t(vh_, sb + VH + va);
                ldsm4t(vl_, sb + VL + va);
                mma_bf16(o[2 * nb],     aph, vh_[0], vh_[1]);
                mma_bf16(o[2 * nb + 1], aph, vh_[2], vh_[3]);
                mma_bf16(o[2 * nb],     aph, vl_[0], vl_[1]);
                mma_bf16(o[2 * nb + 1], aph, vl_[2], vl_[3]);
                mma_bf16(o[2 * nb],     apl, vh_[0], vh_[1]);
                mma_bf16(o[2 * nb + 1], apl, vh_[2], vh_[3]);
            }
        }

        __syncthreads();            // all warps done reading V(j)
        load_V(j + 1);              // hides under next S
    }

    // ---- epilogue: O/l -> bf16 hi/lo ----
    const float inv0 = 1.0f / l0, inv1 = 1.0f / l1;
    const size_t obase = (size_t)b * AT_T * AT_C + (size_t)hd * AT_D;
    #pragma unroll
    for (int nf = 0; nf < 16; nf++) {
        int d = nf * 8 + 2 * (lane & 3);
        u32 h0, lo0, h1, lo1;
        pack2hl(o[nf][0] * inv0, o[nf][1] * inv0, h0, lo0);
        pack2hl(o[nf][2] * inv1, o[nf][3] * inv1, h1, lo1);
        size_t i0 = obase + (size_t)qrow0 * AT_C + d;
        size_t i1 = obase + (size_t)qrow1 * AT_C + d;
        *(u32*)(g_xoh + i0) = h0;  *(u32*)(g_xol + i0) = lo0;
        *(u32*)(g_xoh + i1) = h1;  *(u32*)(g_xol + i1) = lo1;
    }
}

// ---------------------------------------------------------------------------
// Launch: fused split -> merged QKV proj -> TC attention -> out proj
// ---------------------------------------------------------------------------
extern "C" void kernel_launch(void* const* d_in, const int* in_sizes, int n_in,
                              void* d_out, int out_size)
{
    const float* q   = (const float*)d_in[0];
    const float* k   = (const float*)d_in[1];
    const float* v   = (const float*)d_in[2];
    const float* ipw = (const float*)d_in[3];  // (3072, 2048)
    const float* ipb = (const float*)d_in[4];  // (3072,)
    const float* opw = (const float*)d_in[5];  // (2048, 2048)
    const float* opb = (const float*)d_in[6];  // (2048,)
    float* out = (float*)d_out;

    __nv_bfloat16 *qh, *ql, *kh, *kl, *vh, *vl, *wih, *wil, *woh, *wol;
    cudaGetSymbolAddress((void**)&qh, g_qh);   cudaGetSymbolAddress((void**)&ql, g_ql);
    cudaGetSymbolAddress((void**)&kh, g_kh);   cudaGetSymbolAddress((void**)&kl, g_kl);
    cudaGetSymbolAddress((void**)&vh, g_vh);   cudaGetSymbolAddress((void**)&vl, g_vl);
    cudaGetSymbolAddress((void**)&wih, g_wih); cudaGetSymbolAddress((void**)&wil, g_wil);
    cudaGetSymbolAddress((void**)&woh, g_woh); cudaGetSymbolAddress((void**)&wol, g_wol);

    const int attn_smem = 104448;  // (64+64+64) rows x 272 B x hi/lo
    cudaFuncSetAttribute(attn_tc_kernel, cudaFuncAttributeMaxDynamicSharedMemorySize, attn_smem);
    const int gemm_smem = 4 * STAGE_B;  // 98304
    cudaFuncSetAttribute(gemm_mma_proj, cudaFuncAttributeMaxDynamicSharedMemorySize, gemm_smem);
    cudaFuncSetAttribute(gemm_mma_out,  cudaFuncAttributeMaxDynamicSharedMemorySize, gemm_smem);

    dim3 blk(256);
    const int M_BLK = (AT_B * AT_T) / 128;  // 64

    // Fused prep: split inputs + weights into bf16 hi/lo (one launch)
    split_all_kernel<<<4096, 256>>>((const float4*)q, (const float4*)k, (const float4*)v,
                                    (const float4*)ipw, (const float4*)opw,
                                    (uint2*)qh, (uint2*)ql, (uint2*)kh, (uint2*)kl,
                                    (uint2*)vh, (uint2*)vl, (uint2*)wih, (uint2*)wil,
                                    (uint2*)woh, (uint2*)wol);

    // Merged Q+K+V projection (one launch, grid 24 x 64; Q pre-scaled)
    gemm_mma_proj<<<dim3(24, M_BLK), blk, gemm_smem>>>(ipb);

    // Tensor-core causal GQA flash attention (BM=64, occ 2, pipelined K/V)
    attn_tc_kernel<<<dim3(AT_B * AT_H, AT_T / 64), dim3(128), attn_smem>>>();

    // Output projection (fp32 out)
    gemm_mma_out<<<dim3(AT_C / 128, M_BLK), blk, gemm_smem>>>(opb, out);
}

// round 16
// speedup vs baseline: 1.1076x; 1.1076x over previous
#include <cuda_runtime.h>
#include <cuda_bf16.h>
#include <cstdint>
#include <cstddef>

// Problem constants: B=4, T=2048, C=2048, H=16, G=4, HKV=4, D=128, KV=512
#define AT_B   4
#define AT_T   2048
#define AT_C   2048
#define AT_KV  512
#define AT_D   128
#define AT_H   16
#define AT_HKV 4
#define AT_SCALE 0.08838834764831845f  // 1/sqrt(128)

typedef unsigned long long u64;
typedef unsigned int u32;

// ---------------------------------------------------------------------------
// Common helpers
// ---------------------------------------------------------------------------
__device__ __forceinline__ void pack2hl(float x, float y, u32& h, u32& l) {
    __nv_bfloat162 hv = __float22bfloat162_rn(make_float2(x, y));
    float lx = x - __low2float(hv), ly = y - __high2float(hv);
    __nv_bfloat162 lv = __float22bfloat162_rn(make_float2(lx, ly));
    h = *reinterpret_cast<u32*>(&hv);
    l = *reinterpret_cast<u32*>(&lv);
}

// ---- legacy mma helpers (proven R8-R14) ----
__device__ __forceinline__ void ldsm4(u32* r, u32 addr) {
    asm volatile("ldmatrix.sync.aligned.m8n8.x4.shared.b16 {%0,%1,%2,%3}, [%4];"
                 : "=r"(r[0]), "=r"(r[1]), "=r"(r[2]), "=r"(r[3]) : "r"(addr));
}
__device__ __forceinline__ void ldsm4t(u32* r, u32 addr) {
    asm volatile("ldmatrix.sync.aligned.m8n8.x4.trans.shared.b16 {%0,%1,%2,%3}, [%4];"
                 : "=r"(r[0]), "=r"(r[1]), "=r"(r[2]), "=r"(r[3]) : "r"(addr));
}
__device__ __forceinline__ void mma_bf16(float* d, const u32* a, u32 b0, u32 b1) {
    asm volatile("mma.sync.aligned.m16n8k16.row.col.f32.bf16.bf16.f32 "
                 "{%0,%1,%2,%3}, {%4,%5,%6,%7}, {%8,%9}, {%0,%1,%2,%3};"
                 : "+f"(d[0]), "+f"(d[1]), "+f"(d[2]), "+f"(d[3])
                 : "r"(a[0]), "r"(a[1]), "r"(a[2]), "r"(a[3]), "r"(b0), "r"(b1));
}

// ---- cp.async helpers ----
__device__ __forceinline__ void cpa16(u32 s, const void* g) {
    asm volatile("cp.async.cg.shared.global [%0], [%1], 16;" :: "r"(s), "l"(g) : "memory");
}
#define CP_COMMIT() asm volatile("cp.async.commit_group;" ::: "memory")
#define CP_WAIT(n)  asm volatile("cp.async.wait_group %0;" :: "n"(n) : "memory")

// ---------------------------------------------------------------------------
// Scratch (allocation-free rule: __device__ globals)
// ---------------------------------------------------------------------------
__device__ __nv_bfloat16 g_qh[AT_B * AT_T * AT_C], g_ql[AT_B * AT_T * AT_C];
__device__ __nv_bfloat16 g_kh[AT_B * AT_T * AT_C], g_kl[AT_B * AT_T * AT_C];
__device__ __nv_bfloat16 g_vh[AT_B * AT_T * AT_C], g_vl[AT_B * AT_T * AT_C];
__device__ __nv_bfloat16 g_wih[(AT_C + 2 * AT_KV) * AT_C], g_wil[(AT_C + 2 * AT_KV) * AT_C];
__device__ __nv_bfloat16 g_woh[AT_C * AT_C], g_wol[AT_C * AT_C];
__device__ __nv_bfloat16 g_xqh[AT_B * AT_T * AT_C],  g_xql[AT_B * AT_T * AT_C];
__device__ __nv_bfloat16 g_xkh[AT_B * AT_T * AT_KV], g_xkl[AT_B * AT_T * AT_KV];
__device__ __nv_bfloat16 g_xvh[AT_B * AT_T * AT_KV], g_xvl[AT_B * AT_T * AT_KV];
__device__ __nv_bfloat16 g_xoh[AT_B * AT_T * AT_C], g_xol[AT_B * AT_T * AT_C];

// ---------------------------------------------------------------------------
// Fused fp32 -> (bf16 hi, bf16 lo) split over all 5 tensors (one launch)
// ---------------------------------------------------------------------------
#define N_ACT (AT_B * AT_T * AT_C / 4)
#define N_IPW ((AT_C + 2 * AT_KV) * AT_C / 4)
#define N_OPW (AT_C * AT_C / 4)

__global__ void split_all_kernel(const float4* __restrict__ q, const float4* __restrict__ k,
                                 const float4* __restrict__ v, const float4* __restrict__ ipw,
                                 const float4* __restrict__ opw,
                                 uint2* qh, uint2* ql, uint2* kh, uint2* kl,
                                 uint2* vh, uint2* vl, uint2* wih, uint2* wil,
                                 uint2* woh, uint2* wol)
{
    const int total = 3 * N_ACT + N_IPW + N_OPW;
    for (int i = blockIdx.x * blockDim.x + threadIdx.x; i < total; i += gridDim.x * blockDim.x) {
        const float4* src; uint2 *hi, *lo; int j = i;
        if (j < N_ACT)                    { src = q;   hi = qh;  lo = ql;  }
        else if ((j -= N_ACT) < N_ACT)    { src = k;   hi = kh;  lo = kl;  }
        else if ((j -= N_ACT) < N_ACT)    { src = v;   hi = vh;  lo = vl;  }
        else if ((j -= N_ACT) < N_IPW)    { src = ipw; hi = wih; lo = wil; }
        else { j -= N_IPW;                  src = opw; hi = woh; lo = wol; }
        float4 val = src[j];
        u32 h0, l0, h1, l1;
        pack2hl(val.x, val.y, h0, l0);
        pack2hl(val.z, val.w, h1, l1);
        hi[j] = make_uint2(h0, h1);
        lo[j] = make_uint2(l0, l1);
    }
}

// ---------------------------------------------------------------------------
// bf16x3 HMMA GEMM core. R16: R14 structure (full-width pass-major passes,
// 16-MMA accumulator spacing, load_stage at END) with A-fragment streaming
// double buffers (al/ah, 2 deep) so no pass ever stalls on an ldsm WAR.
// All B fragments (hi+lo) loaded up front. Register count unchanged (occ 2).
// ---------------------------------------------------------------------------
#define STAGE_B 24576u

template<bool SPLIT>
__device__ __forceinline__
void gemm_core(const __nv_bfloat16* __restrict__ Ahi, const __nv_bfloat16* __restrict__ Alo,
               const __nv_bfloat16* __restrict__ Whi, const __nv_bfloat16* __restrict__ Wlo,
               const float* __restrict__ bias, float* __restrict__ out,
               __nv_bfloat16* __restrict__ oh, __nv_bfloat16* __restrict__ ol,
               int N, int K, int m0, int n0, float scl)
{
    extern __shared__ __align__(16) char dsm[];
    const u32 sb  = (u32)__cvta_generic_to_shared(dsm);
    const int tid = threadIdx.x;

    auto load_stage = [&](int kt) {
        const u32 base = sb + (u32)(kt & 3) * STAGE_B;
        const int kofs = kt * 16;
        #pragma unroll
        for (int t = 0; t < 2; t++) {
            int j = tid + t * 256;
            int arr = j >> 8, r = (j >> 1) & 127, c = j & 1;
            const __nv_bfloat16* gp = (arr ? Alo : Ahi) + (size_t)(m0 + r) * K + kofs + c * 8;
            cpa16(base + arr * 6144 + r * 48 + c * 16, gp);
        }
        #pragma unroll
        for (int t = 0; t < 2; t++) {
            int j = tid + t * 256;
            int arr = j >> 8, r = (j >> 1) & 127, c = j & 1;
            const __nv_bfloat16* gp = (arr ? Wlo : Whi) + (size_t)(n0 + r) * K + kofs + c * 8;
            cpa16(base + 12288 + arr * 6144 + r * 48 + c * 16, gp);
        }
        CP_COMMIT();
    };

    load_stage(0);
    load_stage(1);
    load_stage(2);

    const int wid  = tid >> 5, lane = tid & 31;
    const int wm   = (wid & 1) << 6;
    const int wn   = (wid >> 1) << 5;

    const u32 a_off = (u32)((wm + (lane & 7) + ((lane >> 3) & 1) * 8) * 48 + (lane >> 4) * 16);
    const u32 b_off = (u32)((wn + (lane & 7) + (lane >> 4) * 8) * 48 + ((lane >> 3) & 1) * 16);

    float acc[4][4][4] = {};

    const int nk = K >> 4;
    for (int kt = 0; kt < nk; kt++) {
        if (kt + 3 < nk) { CP_WAIT(2); } else { CP_WAIT(0); }
        __syncthreads();

        const u32 base = sb + (u32)(kt & 3) * STAGE_B;
        u32 bh[2][4], bl[2][4], al[2][4], ah[2][4];

        // All B fragments (hi + lo) up front
        #pragma unroll
        for (int pf = 0; pf < 2; pf++) {
            ldsm4(bh[pf], base + 12288 + b_off + pf * 768);
            ldsm4(bl[pf], base + 18432 + b_off + pf * 768);
        }
        ldsm4(al[0], base + 6144 + a_off);

        // pass 1: Al * Bh (stream al; tail-prefetch ah[0] for pass 2)
        #pragma unroll
        for (int mf = 0; mf < 4; mf++) {
            const int cur = mf & 1;
            if (mf < 3) ldsm4(al[cur ^ 1], base + 6144 + a_off + (mf + 1) * 768);
            else        ldsm4(ah[0], base + a_off);
            #pragma unroll
            for (int nf = 0; nf < 4; nf++)
                mma_bf16(acc[mf][nf], al[cur], bh[nf >> 1][(nf & 1) * 2], bh[nf >> 1][(nf & 1) * 2 + 1]);
        }

        // pass 2: Ah * Bh (stream ah)
        #pragma unroll
        for (int mf = 0; mf < 4; mf++) {
            const int cur = mf & 1;
            if (mf < 3) ldsm4(ah[cur ^ 1], base + a_off + (mf + 1) * 768);
            #pragma unroll
            for (int nf = 0; nf < 4; nf++)
                mma_bf16(acc[mf][nf], ah[cur], bh[nf >> 1][(nf & 1) * 2], bh[nf >> 1][(nf & 1) * 2 + 1]);
        }
        ldsm4(ah[0], base + a_off);   // re-seed Ah(mf0) for pass 3 (ah[1] just used)

        // pass 3: Ah * Bl (stream ah again)
        #pragma unroll
        for (int mf = 0; mf < 4; mf++) {
            const int cur = mf & 1;
            if (mf < 3) ldsm4(ah[cur ^ 1], base + a_off + (mf + 1) * 768);
            #pragma unroll
            for (int nf = 0; nf < 4; nf++)
                mma_bf16(acc[mf][nf], ah[cur], bl[nf >> 1][(nf & 1) * 2], bl[nf >> 1][(nf & 1) * 2 + 1]);
        }

        if (kt + 3 < nk) load_stage(kt + 3);   // at END: issue overlaps in-flight MMAs
    }

    const int gr  = lane >> 2;
    const int gc2 = (lane & 3) * 2;
    #pragma unroll
    for (int mf = 0; mf < 4; mf++) {
        int row0 = m0 + wm + mf * 16 + gr;
        #pragma unroll
        for (int nf = 0; nf < 4; nf++) {
            int col = n0 + wn + nf * 8 + gc2;
            float2 bv = *(const float2*)(bias + col);
            float v00 = (acc[mf][nf][0] + bv.x) * scl, v01 = (acc[mf][nf][1] + bv.y) * scl;
            float v10 = (acc[mf][nf][2] + bv.x) * scl, v11 = (acc[mf][nf][3] + bv.y) * scl;
            if (SPLIT) {
                u32 h0, l0, h1, l1;
                pack2hl(v00, v01, h0, l0);
                pack2hl(v10, v11, h1, l1);
                *(u32*)(oh + (size_t)row0 * N + col)       = h0;
                *(u32*)(ol + (size_t)row0 * N + col)       = l0;
                *(u32*)(oh + (size_t)(row0 + 8) * N + col) = h1;
                *(u32*)(ol + (size_t)(row0 + 8) * N + col) = l1;
            } else {
                *(float2*)(out + (size_t)row0 * N + col)       = make_float2(v00, v01);
                *(float2*)(out + (size_t)(row0 + 8) * N + col) = make_float2(v10, v11);
            }
        }
    }
}

// Merged Q+K+V projection: grid (24, 64).
__global__ __launch_bounds__(256, 2)
void gemm_mma_proj(const float* __restrict__ ipb)
{
    const int bx = blockIdx.x;
    const __nv_bfloat16 *Ahi, *Alo, *Whi, *Wlo;
    __nv_bfloat16 *oh, *ol;
    const float* bias;
    int N, n0;
    float scl;
    if (bx < 16) {
        Ahi = g_qh; Alo = g_ql; Whi = g_wih; Wlo = g_wil;
        bias = ipb; oh = g_xqh; ol = g_xql; N = AT_C; n0 = bx * 128; scl = AT_SCALE;
    } else if (bx < 20) {
        Ahi = g_kh; Alo = g_kl;
        Whi = g_wih + (size_t)AT_C * AT_C; Wlo = g_wil + (size_t)AT_C * AT_C;
        bias = ipb + AT_C; oh = g_xkh; ol = g_xkl; N = AT_KV; n0 = (bx - 16) * 128; scl = 1.0f;
    } else {
        Ahi = g_vh; Alo = g_vl;
        Whi = g_wih + (size_t)(AT_C + AT_KV) * AT_C; Wlo = g_wil + (size_t)(AT_C + AT_KV) * AT_C;
        bias = ipb + AT_C + AT_KV; oh = g_xvh; ol = g_xvl; N = AT_KV; n0 = (bx - 20) * 128; scl = 1.0f;
    }
    gemm_core<true>(Ahi, Alo, Whi, Wlo, bias, nullptr, oh, ol,
                    N, AT_C, blockIdx.y * 128, n0, scl);
}

// Output projection (fp32 out)
__global__ __launch_bounds__(256, 2)
void gemm_mma_out(const float* __restrict__ opb, float* __restrict__ out)
{
    gemm_core<false>(g_xoh, g_xol, g_woh, g_wol, opb, out, nullptr, nullptr,
                     AT_C, AT_C, blockIdx.y * 128, blockIdx.x * 128, 1.0f);
}

// ---------------------------------------------------------------------------
// Tensor-core flash attention (causal, GQA), bf16x3, BM=64, occ 2.
// Byte-identical to R14 (Q pre-scaled + Q fragments hoisted).
// ---------------------------------------------------------------------------
__global__ __launch_bounds__(128, 2)
void attn_tc_kernel()
{
    extern __shared__ __align__(16) __nv_bfloat16 smx[];
    const u32 sb = (u32)__cvta_generic_to_shared(smx);
    const u32 QH = 0, QL = 17408, KH = 34816, KL = 52224, VH = 69632, VL = 87040;

    const int tid  = threadIdx.x;
    const int wid  = tid >> 5, lane = tid & 31;
    const int bx   = blockIdx.x;
    const int b    = bx >> 4;
    const int hd   = bx & 15;
    const int hkv  = hd & 3;
    const int qb   = 31 - blockIdx.y;          // heavy blocks first
    const int q0   = qb * 64;

    const __nv_bfloat16* qhp = g_xqh + ((size_t)b * AT_T + q0) * AT_C + hd * AT_D;
    const __nv_bfloat16* qlp = g_xql + ((size_t)b * AT_T + q0) * AT_C + hd * AT_D;
    const __nv_bfloat16* khp = g_xkh + (size_t)b * AT_T * AT_KV + hkv * AT_D;
    const __nv_bfloat16* klp = g_xkl + (size_t)b * AT_T * AT_KV + hkv * AT_D;
    const __nv_bfloat16* vhp = g_xvh + (size_t)b * AT_T * AT_KV + hkv * AT_D;
    const __nv_bfloat16* vlp = g_xvl + (size_t)b * AT_T * AT_KV + hkv * AT_D;

    auto load_K = [&](int j) {
        if (j <= qb) {
            for (int i = tid; i < 1024; i += 128) {
                int row = i >> 4, cc = (i & 15) << 3;
                size_t g = (size_t)(j * 64 + row) * AT_KV + cc;
                u32 so = row * 272 + cc * 2;
                cpa16(sb + KH + so, khp + g);
                cpa16(sb + KL + so, klp + g);
            }
        }
        CP_COMMIT();
    };
    auto load_V = [&](int j) {
        if (j <= qb) {
            for (int i = tid; i < 1024; i += 128) {
                int row = i >> 4, cc = (i & 15) << 3;
                size_t g = (size_t)(j * 64 + row) * AT_KV + cc;
                u32 so = row * 272 + cc * 2;
                cpa16(sb + VH + so, vhp + g);
                cpa16(sb + VL + so, vlp + g);
            }
        }
        CP_COMMIT();
    };

    // Q tile (64 x 128 halves, hi+lo)
    for (int i = tid; i < 1024; i += 128) {
        int row = i >> 4, cc = (i & 15) << 3;
        size_t g = (size_t)row * AT_C + cc;
        cpa16(sb + QH + row * 272 + cc * 2, qhp + g);
        cpa16(sb + QL + row * 272 + cc * 2, qlp + g);
    }
    CP_COMMIT();
    load_K(0);
    load_V(0);

    const int wq = wid * 16;
    const int gr = lane >> 2;
    const int qrow0 = q0 + wq + gr;
    const int qrow1 = qrow0 + 8;

    const u32 a_off = (u32)((wq + (lane & 7) + ((lane >> 3) & 1) * 8) * 272 + (lane >> 4) * 16);
    const u32 b_off = (u32)(((lane & 7) + (lane >> 4) * 8) * 272 + ((lane >> 3) & 1) * 16);
    const u32 v_off = (u32)(((lane & 7) + ((lane >> 3) & 1) * 8) * 272 + (lane >> 4) * 16);

    // Hoist Q fragments (tile-invariant) into registers
    u32 qah[8][4], qal[8][4];
    CP_WAIT(2);          // Q group complete (K0/V0 may be in flight)
    __syncthreads();
    #pragma unroll
    for (int c = 0; c < 8; c++) {
        ldsm4(qah[c], sb + QH + a_off + c * 32);
        ldsm4(qal[c], sb + QL + a_off + c * 32);
    }

    float o[16][4];
    #pragma unroll
    for (int nf = 0; nf < 16; nf++)
        #pragma unroll
        for (int k = 0; k < 4; k++) o[nf][k] = 0.f;
    float m0 = -1e30f, m1 = -1e30f, l0 = 0.f, l1 = 0.f;

    for (int j = 0; j <= qb; j++) {
        // K(j) complete; V(j) may still be in flight
        CP_WAIT(1);
        __syncthreads();

        // ---- S = Q K^T (bf16x3; Q from registers) ----
        float s[8][4];
        #pragma unroll
        for (int nf = 0; nf < 8; nf++)
            #pragma unroll
            for (int k = 0; k < 4; k++) s[nf][k] = 0.f;

        #pragma unroll
        for (int c = 0; c < 8; c++) {
            #pragma unroll
            for (int nb = 0; nb < 4; nb++) {
                u32 bh_[4], bl_[4];
                u32 ka = b_off + nb * 4352 + c * 32;
                ldsm4(bh_, sb + KH + ka);
                ldsm4(bl_, sb + KL + ka);
                mma_bf16(s[2 * nb],     qal[c], bh_[0], bh_[1]);
                mma_bf16(s[2 * nb + 1], qal[c], bh_[2], bh_[3]);
                mma_bf16(s[2 * nb],     qah[c], bl_[0], bl_[1]);
                mma_bf16(s[2 * nb + 1], qah[c], bl_[2], bl_[3]);
                mma_bf16(s[2 * nb],     qah[c], bh_[0], bh_[1]);
                mma_bf16(s[2 * nb + 1], qah[c], bh_[2], bh_[3]);
            }
        }

        __syncthreads();            // all warps done reading K(j)
        load_K(j + 1);              // hides under softmax + PV

        // ---- online softmax (Q pre-scaled; no scale muls) ----
        const bool maskt = (j == qb);
        const int colb = j * 64 + 2 * (lane & 3);
        float mx0 = -1e30f, mx1 = -1e30f;
        #pragma unroll
        for (int nf = 0; nf < 8; nf++) {
            int c0 = colb + 8 * nf;
            if (maskt) {
                if (c0     > qrow0) s[nf][0] = -1e30f;
                if (c0 + 1 > qrow0) s[nf][1] = -1e30f;
                if (c0     > qrow1) s[nf][2] = -1e30f;
                if (c0 + 1 > qrow1) s[nf][3] = -1e30f;
            }
            mx0 = fmaxf(mx0, fmaxf(s[nf][0], s[nf][1]));
            mx1 = fmaxf(mx1, fmaxf(s[nf][2], s[nf][3]));
        }
        mx0 = fmaxf(mx0, __shfl_xor_sync(0xffffffffu, mx0, 1));
        mx0 = fmaxf(mx0, __shfl_xor_sync(0xffffffffu, mx0, 2));
        mx1 = fmaxf(mx1, __shfl_xor_sync(0xffffffffu, mx1, 1));
        mx1 = fmaxf(mx1, __shfl_xor_sync(0xffffffffu, mx1, 2));

        float nm0 = fmaxf(m0, mx0), nm1 = fmaxf(m1, mx1);
        float corr0 = __expf(m0 - nm0), corr1 = __expf(m1 - nm1);
        m0 = nm0; m1 = nm1;

        float rs0 = 0.f, rs1 = 0.f;
        #pragma unroll
        for (int nf = 0; nf < 8; nf++) {
            s[nf][0] = __expf(s[nf][0] - m0); rs0 += s[nf][0];
            s[nf][1] = __expf(s[nf][1] - m0); rs0 += s[nf][1];
            s[nf][2] = __expf(s[nf][2] - m1); rs1 += s[nf][2];
            s[nf][3] = __expf(s[nf][3] - m1); rs1 += s[nf][3];
        }
        rs0 += __shfl_xor_sync(0xffffffffu, rs0, 1);
        rs0 += __shfl_xor_sync(0xffffffffu, rs0, 2);
        rs1 += __shfl_xor_sync(0xffffffffu, rs1, 1);
        rs1 += __shfl_xor_sync(0xffffffffu, rs1, 2);
        l0 = l0 * corr0 + rs0;
        l1 = l1 * corr1 + rs1;

        #pragma unroll
        for (int nf = 0; nf < 16; nf++) {
            o[nf][0] *= corr0; o[nf][1] *= corr0;
            o[nf][2] *= corr1; o[nf][3] *= corr1;
        }

        // V(j) complete (K(j+1) may still be in flight)
        CP_WAIT(1);
        __syncthreads();

        // ---- O += P V (bf16x3) ----
        #pragma unroll
        for (int c = 0; c < 4; c++) {
            u32 aph[4], apl[4];
            pack2hl(s[2 * c][0],     s[2 * c][1],     aph[0], apl[0]);
            pack2hl(s[2 * c][2],     s[2 * c][3],     aph[1], apl[1]);
            pack2hl(s[2 * c + 1][0], s[2 * c + 1][1], aph[2], apl[2]);
            pack2hl(s[2 * c + 1][2], s[2 * c + 1][3], aph[3], apl[3]);
            #pragma unroll
            for (int nb = 0; nb < 8; nb++) {
                u32 vh_[4], vl_[4];
                u32 va = v_off + c * 4352 + nb * 32;
                ldsm4t(vh_, sb + VH + va);
                ldsm4t(vl_, sb + VL + va);
                mma_bf16(o[2 * nb],     aph, vh_[0], vh_[1]);
                mma_bf16(o[2 * nb + 1], aph, vh_[2], vh_[3]);
                mma_bf16(o[2 * nb],     aph, vl_[0], vl_[1]);
                mma_bf16(o[2 * nb + 1], aph, vl_[2], vl_[3]);
                mma_bf16(o[2 * nb],     apl, vh_[0], vh_[1]);
                mma_bf16(o[2 * nb + 1], apl, vh_[2], vh_[3]);
            }
        }

        __syncthreads();            // all warps done reading V(j)
        load_V(j + 1);              // hides under next S
    }

    // ---- epilogue: O/l -> bf16 hi/lo ----
    const float inv0 = 1.0f / l0, inv1 = 1.0f / l1;
    const size_t obase = (size_t)b * AT_T * AT_C + (size_t)hd * AT_D;
    #pragma unroll
    for (int nf = 0; nf < 16; nf++) {
        int d = nf * 8 + 2 * (lane & 3);
        u32 h0, lo0, h1, lo1;
        pack2hl(o[nf][0] * inv0, o[nf][1] * inv0, h0, lo0);
        pack2hl(o[nf][2] * inv1, o[nf][3] * inv1, h1, lo1);
        size_t i0 = obase + (size_t)qrow0 * AT_C + d;
        size_t i1 = obase + (size_t)qrow1 * AT_C + d;
        *(u32*)(g_xoh + i0) = h0;  *(u32*)(g_xol + i0) = lo0;
        *(u32*)(g_xoh + i1) = h1;  *(u32*)(g_xol + i1) = lo1;
    }
}

// ---------------------------------------------------------------------------
// Launch: fused split -> merged QKV proj -> TC attention -> out proj
// ---------------------------------------------------------------------------
extern "C" void kernel_launch(void* const* d_in, const int* in_sizes, int n_in,
                              void* d_out, int out_size)
{
    const float* q   = (const float*)d_in[0];
    const float* k   = (const float*)d_in[1];
    const float* v   = (const float*)d_in[2];
    const float* ipw = (const float*)d_in[3];  // (3072, 2048)
    const float* ipb = (const float*)d_in[4];  // (3072,)
    const float* opw = (const float*)d_in[5];  // (2048, 2048)
    const float* opb = (const float*)d_in[6];  // (2048,)
    float* out = (float*)d_out;

    __nv_bfloat16 *qh, *ql, *kh, *kl, *vh, *vl, *wih, *wil, *woh, *wol;
    cudaGetSymbolAddress((void**)&qh, g_qh);   cudaGetSymbolAddress((void**)&ql, g_ql);
    cudaGetSymbolAddress((void**)&kh, g_kh);   cudaGetSymbolAddress((void**)&kl, g_kl);
    cudaGetSymbolAddress((void**)&vh, g_vh);   cudaGetSymbolAddress((void**)&vl, g_vl);
    cudaGetSymbolAddress((void**)&wih, g_wih); cudaGetSymbolAddress((void**)&wil, g_wil);
    cudaGetSymbolAddress((void**)&woh, g_woh); cudaGetSymbolAddress((void**)&wol, g_wol);

    const int attn_smem = 104448;  // (64+64+64) rows x 272 B x hi/lo
    cudaFuncSetAttribute(attn_tc_kernel, cudaFuncAttributeMaxDynamicSharedMemorySize, attn_smem);
    const int gemm_smem = 4 * STAGE_B;  // 98304
    cudaFuncSetAttribute(gemm_mma_proj, cudaFuncAttributeMaxDynamicSharedMemorySize, gemm_smem);
    cudaFuncSetAttribute(gemm_mma_out,  cudaFuncAttributeMaxDynamicSharedMemorySize, gemm_smem);

    dim3 blk(256);
    const int M_BLK = (AT_B * AT_T) / 128;  // 64

    // Fused prep: split inputs + weights into bf16 hi/lo (one launch)
    split_all_kernel<<<4096, 256>>>((const float4*)q, (const float4*)k, (const float4*)v,
                                    (const float4*)ipw, (const float4*)opw,
                                    (uint2*)qh, (uint2*)ql, (uint2*)kh, (uint2*)kl,
                                    (uint2*)vh, (uint2*)vl, (uint2*)wih, (uint2*)wil,
                                    (uint2*)woh, (uint2*)wol);

    // Merged Q+K+V projection (one launch, grid 24 x 64; Q pre-scaled)
    gemm_mma_proj<<<dim3(24, M_BLK), blk, gemm_smem>>>(ipb);

    // Tensor-core causal GQA flash attention (BM=64, occ 2, pipelined K/V)
    attn_tc_kernel<<<dim3(AT_B * AT_H, AT_T / 64), dim3(128), attn_smem>>>();

    // Output projection (fp32 out)
    gemm_mma_out<<<dim3(AT_C / 128, M_BLK), blk, gemm_smem>>>(opb, out);
}

// round 17
// speedup vs baseline: 1.1419x; 1.0310x over previous
#include <cuda_runtime.h>
#include <cuda_bf16.h>
#include <cstdint>
#include <cstddef>

// Problem constants: B=4, T=2048, C=2048, H=16, G=4, HKV=4, D=128, KV=512
#define AT_B   4
#define AT_T   2048
#define AT_C   2048
#define AT_KV  512
#define AT_D   128
#define AT_H   16
#define AT_HKV 4
#define AT_SCALE 0.08838834764831845f            // 1/sqrt(128)
#define AT_SCALE_LOG2E 0.1275179371652247f       // AT_SCALE * log2(e)

typedef unsigned long long u64;
typedef unsigned int u32;

// ---------------------------------------------------------------------------
// Common helpers
// ---------------------------------------------------------------------------
__device__ __forceinline__ void pack2hl(float x, float y, u32& h, u32& l) {
    __nv_bfloat162 hv = __float22bfloat162_rn(make_float2(x, y));
    float lx = x - __low2float(hv), ly = y - __high2float(hv);
    __nv_bfloat162 lv = __float22bfloat162_rn(make_float2(lx, ly));
    h = *reinterpret_cast<u32*>(&hv);
    l = *reinterpret_cast<u32*>(&lv);
}
__device__ __forceinline__ u64 fmul2(u64 a, u64 b) {
    u64 d;
    asm("mul.rn.f32x2 %0, %1, %2;" : "=l"(d) : "l"(a), "l"(b));
    return d;
}
__device__ __forceinline__ u64 dup2(float x) {
    u64 r;
    asm("mov.b64 %0, {%1, %1};" : "=l"(r) : "f"(x));
    return r;
}

// ---- legacy mma helpers (proven R8-R14) ----
__device__ __forceinline__ void ldsm4(u32* r, u32 addr) {
    asm volatile("ldmatrix.sync.aligned.m8n8.x4.shared.b16 {%0,%1,%2,%3}, [%4];"
                 : "=r"(r[0]), "=r"(r[1]), "=r"(r[2]), "=r"(r[3]) : "r"(addr));
}
__device__ __forceinline__ void ldsm4t(u32* r, u32 addr) {
    asm volatile("ldmatrix.sync.aligned.m8n8.x4.trans.shared.b16 {%0,%1,%2,%3}, [%4];"
                 : "=r"(r[0]), "=r"(r[1]), "=r"(r[2]), "=r"(r[3]) : "r"(addr));
}
__device__ __forceinline__ void mma_bf16(float* d, const u32* a, u32 b0, u32 b1) {
    asm volatile("mma.sync.aligned.m16n8k16.row.col.f32.bf16.bf16.f32 "
                 "{%0,%1,%2,%3}, {%4,%5,%6,%7}, {%8,%9}, {%0,%1,%2,%3};"
                 : "+f"(d[0]), "+f"(d[1]), "+f"(d[2]), "+f"(d[3])
                 : "r"(a[0]), "r"(a[1]), "r"(a[2]), "r"(a[3]), "r"(b0), "r"(b1));
}

// ---- cp.async helpers ----
__device__ __forceinline__ void cpa16(u32 s, const void* g) {
    asm volatile("cp.async.cg.shared.global [%0], [%1], 16;" :: "r"(s), "l"(g) : "memory");
}
#define CP_COMMIT() asm volatile("cp.async.commit_group;" ::: "memory")
#define CP_WAIT(n)  asm volatile("cp.async.wait_group %0;" :: "n"(n) : "memory")

// ---------------------------------------------------------------------------
// Scratch (allocation-free rule: __device__ globals)
// ---------------------------------------------------------------------------
__device__ __nv_bfloat16 g_qh[AT_B * AT_T * AT_C], g_ql[AT_B * AT_T * AT_C];
__device__ __nv_bfloat16 g_kh[AT_B * AT_T * AT_C], g_kl[AT_B * AT_T * AT_C];
__device__ __nv_bfloat16 g_vh[AT_B * AT_T * AT_C], g_vl[AT_B * AT_T * AT_C];
__device__ __nv_bfloat16 g_wih[(AT_C + 2 * AT_KV) * AT_C], g_wil[(AT_C + 2 * AT_KV) * AT_C];
__device__ __nv_bfloat16 g_woh[AT_C * AT_C], g_wol[AT_C * AT_C];
__device__ __nv_bfloat16 g_xqh[AT_B * AT_T * AT_C],  g_xql[AT_B * AT_T * AT_C];
__device__ __nv_bfloat16 g_xkh[AT_B * AT_T * AT_KV], g_xkl[AT_B * AT_T * AT_KV];
__device__ __nv_bfloat16 g_xvh[AT_B * AT_T * AT_KV], g_xvl[AT_B * AT_T * AT_KV];
__device__ __nv_bfloat16 g_xoh[AT_B * AT_T * AT_C], g_xol[AT_B * AT_T * AT_C];

// ---------------------------------------------------------------------------
// Fused fp32 -> (bf16 hi, bf16 lo) split over all 5 tensors (one launch)
// ---------------------------------------------------------------------------
#define N_ACT (AT_B * AT_T * AT_C / 4)
#define N_IPW ((AT_C + 2 * AT_KV) * AT_C / 4)
#define N_OPW (AT_C * AT_C / 4)

__global__ void split_all_kernel(const float4* __restrict__ q, const float4* __restrict__ k,
                                 const float4* __restrict__ v, const float4* __restrict__ ipw,
                                 const float4* __restrict__ opw,
                                 uint2* qh, uint2* ql, uint2* kh, uint2* kl,
                                 uint2* vh, uint2* vl, uint2* wih, uint2* wil,
                                 uint2* woh, uint2* wol)
{
    const int total = 3 * N_ACT + N_IPW + N_OPW;
    for (int i = blockIdx.x * blockDim.x + threadIdx.x; i < total; i += gridDim.x * blockDim.x) {
        const float4* src; uint2 *hi, *lo; int j = i;
        if (j < N_ACT)                    { src = q;   hi = qh;  lo = ql;  }
        else if ((j -= N_ACT) < N_ACT)    { src = k;   hi = kh;  lo = kl;  }
        else if ((j -= N_ACT) < N_ACT)    { src = v;   hi = vh;  lo = vl;  }
        else if ((j -= N_ACT) < N_IPW)    { src = ipw; hi = wih; lo = wil; }
        else { j -= N_IPW;                  src = opw; hi = woh; lo = wol; }
        float4 val = src[j];
        u32 h0, l0, h1, l1;
        pack2hl(val.x, val.y, h0, l0);
        pack2hl(val.z, val.w, h1, l1);
        hi[j] = make_uint2(h0, h1);
        lo[j] = make_uint2(l0, l1);
    }
}

// ---------------------------------------------------------------------------
// bf16x3 HMMA GEMM core — EXACT R14 body (the empirically fastest variant:
// single af[4][4] reused across passes, load_stage at END of iteration).
// ---------------------------------------------------------------------------
#define STAGE_B 24576u

template<bool SPLIT>
__device__ __forceinline__
void gemm_core(const __nv_bfloat16* __restrict__ Ahi, const __nv_bfloat16* __restrict__ Alo,
               const __nv_bfloat16* __restrict__ Whi, const __nv_bfloat16* __restrict__ Wlo,
               const float* __restrict__ bias, float* __restrict__ out,
               __nv_bfloat16* __restrict__ oh, __nv_bfloat16* __restrict__ ol,
               int N, int K, int m0, int n0, float scl)
{
    extern __shared__ __align__(16) char dsm[];
    const u32 sb  = (u32)__cvta_generic_to_shared(dsm);
    const int tid = threadIdx.x;

    auto load_stage = [&](int kt) {
        const u32 base = sb + (u32)(kt & 3) * STAGE_B;
        const int kofs = kt * 16;
        #pragma unroll
        for (int t = 0; t < 2; t++) {
            int j = tid + t * 256;
            int arr = j >> 8, r = (j >> 1) & 127, c = j & 1;
            const __nv_bfloat16* gp = (arr ? Alo : Ahi) + (size_t)(m0 + r) * K + kofs + c * 8;
            cpa16(base + arr * 6144 + r * 48 + c * 16, gp);
        }
        #pragma unroll
        for (int t = 0; t < 2; t++) {
            int j = tid + t * 256;
            int arr = j >> 8, r = (j >> 1) & 127, c = j & 1;
            const __nv_bfloat16* gp = (arr ? Wlo : Whi) + (size_t)(n0 + r) * K + kofs + c * 8;
            cpa16(base + 12288 + arr * 6144 + r * 48 + c * 16, gp);
        }
        CP_COMMIT();
    };

    load_stage(0);
    load_stage(1);
    load_stage(2);

    const int wid  = tid >> 5, lane = tid & 31;
    const int wm   = (wid & 1) << 6;
    const int wn   = (wid >> 1) << 5;

    const u32 a_off = (u32)((wm + (lane & 7) + ((lane >> 3) & 1) * 8) * 48 + (lane >> 4) * 16);
    const u32 b_off = (u32)((wn + (lane & 7) + (lane >> 4) * 8) * 48 + ((lane >> 3) & 1) * 16);

    float acc[4][4][4] = {};

    const int nk = K >> 4;
    for (int kt = 0; kt < nk; kt++) {
        if (kt + 3 < nk) { CP_WAIT(2); } else { CP_WAIT(0); }
        __syncthreads();

        const u32 base = sb + (u32)(kt & 3) * STAGE_B;
        u32 af[4][4], bh[2][4], bl[2][4];

        #pragma unroll
        for (int mf = 0; mf < 4; mf++) ldsm4(af[mf], base + 6144 + a_off + mf * 768);
        #pragma unroll
        for (int pf = 0; pf < 2; pf++) ldsm4(bh[pf], base + 12288 + b_off + pf * 768);
        #pragma unroll
        for (int mf = 0; mf < 4; mf++)
            #pragma unroll
            for (int nf = 0; nf < 4; nf++)
                mma_bf16(acc[mf][nf], af[mf], bh[nf >> 1][(nf & 1) * 2], bh[nf >> 1][(nf & 1) * 2 + 1]);

        #pragma unroll
        for (int mf = 0; mf < 4; mf++) ldsm4(af[mf], base + a_off + mf * 768);
        #pragma unroll
        for (int mf = 0; mf < 4; mf++)
            #pragma unroll
            for (int nf = 0; nf < 4; nf++)
                mma_bf16(acc[mf][nf], af[mf], bh[nf >> 1][(nf & 1) * 2], bh[nf >> 1][(nf & 1) * 2 + 1]);

        #pragma unroll
        for (int pf = 0; pf < 2; pf++) ldsm4(bl[pf], base + 18432 + b_off + pf * 768);
        #pragma unroll
        for (int mf = 0; mf < 4; mf++)
            #pragma unroll
            for (int nf = 0; nf < 4; nf++)
                mma_bf16(acc[mf][nf], af[mf], bl[nf >> 1][(nf & 1) * 2], bl[nf >> 1][(nf & 1) * 2 + 1]);

        if (kt + 3 < nk) load_stage(kt + 3);
    }

    const int gr  = lane >> 2;
    const int gc2 = (lane & 3) * 2;
    #pragma unroll
    for (int mf = 0; mf < 4; mf++) {
        int row0 = m0 + wm + mf * 16 + gr;
        #pragma unroll
        for (int nf = 0; nf < 4; nf++) {
            int col = n0 + wn + nf * 8 + gc2;
            float2 bv = *(const float2*)(bias + col);
            float v00 = (acc[mf][nf][0] + bv.x) * scl, v01 = (acc[mf][nf][1] + bv.y) * scl;
            float v10 = (acc[mf][nf][2] + bv.x) * scl, v11 = (acc[mf][nf][3] + bv.y) * scl;
            if (SPLIT) {
                u32 h0, l0, h1, l1;
                pack2hl(v00, v01, h0, l0);
                pack2hl(v10, v11, h1, l1);
                *(u32*)(oh + (size_t)row0 * N + col)       = h0;
                *(u32*)(ol + (size_t)row0 * N + col)       = l0;
                *(u32*)(oh + (size_t)(row0 + 8) * N + col) = h1;
                *(u32*)(ol + (size_t)(row0 + 8) * N + col) = l1;
            } else {
                *(float2*)(out + (size_t)row0 * N + col)       = make_float2(v00, v01);
                *(float2*)(out + (size_t)(row0 + 8) * N + col) = make_float2(v10, v11);
            }
        }
    }
}

// Merged Q+K+V projection: grid (24, 64).
//   bx in [0,16)  -> Q proj, output pre-scaled by 1/sqrt(D)*log2(e)  (log2-domain softmax)
//   bx in [16,20) -> K proj
//   bx in [20,24) -> V proj
__global__ __launch_bounds__(256, 2)
void gemm_mma_proj(const float* __restrict__ ipb)
{
    const int bx = blockIdx.x;
    const __nv_bfloat16 *Ahi, *Alo, *Whi, *Wlo;
    __nv_bfloat16 *oh, *ol;
    const float* bias;
    int N, n0;
    float scl;
    if (bx < 16) {
        Ahi = g_qh; Alo = g_ql; Whi = g_wih; Wlo = g_wil;
        bias = ipb; oh = g_xqh; ol = g_xql; N = AT_C; n0 = bx * 128; scl = AT_SCALE_LOG2E;
    } else if (bx < 20) {
        Ahi = g_kh; Alo = g_kl;
        Whi = g_wih + (size_t)AT_C * AT_C; Wlo = g_wil + (size_t)AT_C * AT_C;
        bias = ipb + AT_C; oh = g_xkh; ol = g_xkl; N = AT_KV; n0 = (bx - 16) * 128; scl = 1.0f;
    } else {
        Ahi = g_vh; Alo = g_vl;
        Whi = g_wih + (size_t)(AT_C + AT_KV) * AT_C; Wlo = g_wil + (size_t)(AT_C + AT_KV) * AT_C;
        bias = ipb + AT_C + AT_KV; oh = g_xvh; ol = g_xvl; N = AT_KV; n0 = (bx - 20) * 128; scl = 1.0f;
    }
    gemm_core<true>(Ahi, Alo, Whi, Wlo, bias, nullptr, oh, ol,
                    N, AT_C, blockIdx.y * 128, n0, scl);
}

// Output projection (fp32 out)
__global__ __launch_bounds__(256, 2)
void gemm_mma_out(const float* __restrict__ opb, float* __restrict__ out)
{
    gemm_core<false>(g_xoh, g_xol, g_woh, g_wol, opb, out, nullptr, nullptr,
                     AT_C, AT_C, blockIdx.y * 128, blockIdx.x * 128, 1.0f);
}

// ---------------------------------------------------------------------------
// Tensor-core flash attention (causal, GQA), bf16x3, BM=64, occ 2.
// R17: log2-domain softmax (Q pre-scaled by scale*log2e -> bare exp2f),
// O-correction via packed f32x2 muls. Otherwise identical to R14.
// ---------------------------------------------------------------------------
__global__ __launch_bounds__(128, 2)
void attn_tc_kernel()
{
    extern __shared__ __align__(16) __nv_bfloat16 smx[];
    const u32 sb = (u32)__cvta_generic_to_shared(smx);
    const u32 QH = 0, QL = 17408, KH = 34816, KL = 52224, VH = 69632, VL = 87040;

    const int tid  = threadIdx.x;
    const int wid  = tid >> 5, lane = tid & 31;
    const int bx   = blockIdx.x;
    const int b    = bx >> 4;
    const int hd   = bx & 15;
    const int hkv  = hd & 3;
    const int qb   = 31 - blockIdx.y;          // heavy blocks first
    const int q0   = qb * 64;

    const __nv_bfloat16* qhp = g_xqh + ((size_t)b * AT_T + q0) * AT_C + hd * AT_D;
    const __nv_bfloat16* qlp = g_xql + ((size_t)b * AT_T + q0) * AT_C + hd * AT_D;
    const __nv_bfloat16* khp = g_xkh + (size_t)b * AT_T * AT_KV + hkv * AT_D;
    const __nv_bfloat16* klp = g_xkl + (size_t)b * AT_T * AT_KV + hkv * AT_D;
    const __nv_bfloat16* vhp = g_xvh + (size_t)b * AT_T * AT_KV + hkv * AT_D;
    const __nv_bfloat16* vlp = g_xvl + (size_t)b * AT_T * AT_KV + hkv * AT_D;

    auto load_K = [&](int j) {
        if (j <= qb) {
            for (int i = tid; i < 1024; i += 128) {
                int row = i >> 4, cc = (i & 15) << 3;
                size_t g = (size_t)(j * 64 + row) * AT_KV + cc;
                u32 so = row * 272 + cc * 2;
                cpa16(sb + KH + so, khp + g);
                cpa16(sb + KL + so, klp + g);
            }
        }
        CP_COMMIT();
    };
    auto load_V = [&](int j) {
        if (j <= qb) {
            for (int i = tid; i < 1024; i += 128) {
                int row = i >> 4, cc = (i & 15) << 3;
                size_t g = (size_t)(j * 64 + row) * AT_KV + cc;
                u32 so = row * 272 + cc * 2;
                cpa16(sb + VH + so, vhp + g);
                cpa16(sb + VL + so, vlp + g);
            }
        }
        CP_COMMIT();
    };

    // Q tile (64 x 128 halves, hi+lo)
    for (int i = tid; i < 1024; i += 128) {
        int row = i >> 4, cc = (i & 15) << 3;
        size_t g = (size_t)row * AT_C + cc;
        cpa16(sb + QH + row * 272 + cc * 2, qhp + g);
        cpa16(sb + QL + row * 272 + cc * 2, qlp + g);
    }
    CP_COMMIT();
    load_K(0);
    load_V(0);

    const int wq = wid * 16;
    const int gr = lane >> 2;
    const int qrow0 = q0 + wq + gr;
    const int qrow1 = qrow0 + 8;

    const u32 a_off = (u32)((wq + (lane & 7) + ((lane >> 3) & 1) * 8) * 272 + (lane >> 4) * 16);
    const u32 b_off = (u32)(((lane & 7) + (lane >> 4) * 8) * 272 + ((lane >> 3) & 1) * 16);
    const u32 v_off = (u32)(((lane & 7) + ((lane >> 3) & 1) * 8) * 272 + (lane >> 4) * 16);

    // Hoist Q fragments (tile-invariant) into registers
    u32 qah[8][4], qal[8][4];
    CP_WAIT(2);          // Q group complete (K0/V0 may be in flight)
    __syncthreads();
    #pragma unroll
    for (int c = 0; c < 8; c++) {
        ldsm4(qah[c], sb + QH + a_off + c * 32);
        ldsm4(qal[c], sb + QL + a_off + c * 32);
    }

    float o[16][4];
    #pragma unroll
    for (int nf = 0; nf < 16; nf++)
        #pragma unroll
        for (int k = 0; k < 4; k++) o[nf][k] = 0.f;
    float m0 = -1e30f, m1 = -1e30f, l0 = 0.f, l1 = 0.f;

    for (int j = 0; j <= qb; j++) {
        // K(j) complete; V(j) may still be in flight
        CP_WAIT(1);
        __syncthreads();

        // ---- S = Q K^T (bf16x3; Q from registers; S is in log2 units) ----
        float s[8][4];
        #pragma unroll
        for (int nf = 0; nf < 8; nf++)
            #pragma unroll
            for (int k = 0; k < 4; k++) s[nf][k] = 0.f;

        #pragma unroll
        for (int c = 0; c < 8; c++) {
            #pragma unroll
            for (int nb = 0; nb < 4; nb++) {
                u32 bh_[4], bl_[4];
                u32 ka = b_off + nb * 4352 + c * 32;
                ldsm4(bh_, sb + KH + ka);
                ldsm4(bl_, sb + KL + ka);
                mma_bf16(s[2 * nb],     qal[c], bh_[0], bh_[1]);
                mma_bf16(s[2 * nb + 1], qal[c], bh_[2], bh_[3]);
                mma_bf16(s[2 * nb],     qah[c], bl_[0], bl_[1]);
                mma_bf16(s[2 * nb + 1], qah[c], bl_[2], bl_[3]);
                mma_bf16(s[2 * nb],     qah[c], bh_[0], bh_[1]);
                mma_bf16(s[2 * nb + 1], qah[c], bh_[2], bh_[3]);
            }
        }

        __syncthreads();            // all warps done reading K(j)
        load_K(j + 1);              // hides under softmax + PV

        // ---- online softmax in log2 domain (bare exp2f) ----
        const bool maskt = (j == qb);
        const int colb = j * 64 + 2 * (lane & 3);
        float mx0 = -1e30f, mx1 = -1e30f;
        #pragma unroll
        for (int nf = 0; nf < 8; nf++) {
            int c0 = colb + 8 * nf;
            if (maskt) {
                if (c0     > qrow0) s[nf][0] = -1e30f;
                if (c0 + 1 > qrow0) s[nf][1] = -1e30f;
                if (c0     > qrow1) s[nf][2] = -1e30f;
                if (c0 + 1 > qrow1) s[nf][3] = -1e30f;
            }
            mx0 = fmaxf(mx0, fmaxf(s[nf][0], s[nf][1]));
            mx1 = fmaxf(mx1, fmaxf(s[nf][2], s[nf][3]));
        }
        mx0 = fmaxf(mx0, __shfl_xor_sync(0xffffffffu, mx0, 1));
        mx0 = fmaxf(mx0, __shfl_xor_sync(0xffffffffu, mx0, 2));
        mx1 = fmaxf(mx1, __shfl_xor_sync(0xffffffffu, mx1, 1));
        mx1 = fmaxf(mx1, __shfl_xor_sync(0xffffffffu, mx1, 2));

        float nm0 = fmaxf(m0, mx0), nm1 = fmaxf(m1, mx1);
        float corr0 = exp2f(m0 - nm0), corr1 = exp2f(m1 - nm1);
        m0 = nm0; m1 = nm1;

        float rs0 = 0.f, rs1 = 0.f;
        #pragma unroll
        for (int nf = 0; nf < 8; nf++) {
            s[nf][0] = exp2f(s[nf][0] - m0); rs0 += s[nf][0];
            s[nf][1] = exp2f(s[nf][1] - m0); rs0 += s[nf][1];
            s[nf][2] = exp2f(s[nf][2] - m1); rs1 += s[nf][2];
            s[nf][3] = exp2f(s[nf][3] - m1); rs1 += s[nf][3];
        }
        rs0 += __shfl_xor_sync(0xffffffffu, rs0, 1);
        rs0 += __shfl_xor_sync(0xffffffffu, rs0, 2);
        rs1 += __shfl_xor_sync(0xffffffffu, rs1, 1);
        rs1 += __shfl_xor_sync(0xffffffffu, rs1, 2);
        l0 = l0 * corr0 + rs0;
        l1 = l1 * corr1 + rs1;

        // O *= corr (packed f32x2: o[nf][0..1] share corr0, o[nf][2..3] corr1)
        {
            u64 c0p = dup2(corr0), c1p = dup2(corr1);
            #pragma unroll
            for (int nf = 0; nf < 16; nf++) {
                u64* op = reinterpret_cast<u64*>(o[nf]);
                op[0] = fmul2(op[0], c0p);
                op[1] = fmul2(op[1], c1p);
            }
        }

        // V(j) complete (K(j+1) may still be in flight)
        CP_WAIT(1);
        __syncthreads();

        // ---- O += P V (bf16x3) ----
        #pragma unroll
        for (int c = 0; c < 4; c++) {
            u32 aph[4], apl[4];
            pack2hl(s[2 * c][0],     s[2 * c][1],     aph[0], apl[0]);
            pack2hl(s[2 * c][2],     s[2 * c][3],     aph[1], apl[1]);
            pack2hl(s[2 * c + 1][0], s[2 * c + 1][1], aph[2], apl[2]);
            pack2hl(s[2 * c + 1][2], s[2 * c + 1][3], aph[3], apl[3]);
            #pragma unroll
            for (int nb = 0; nb < 8; nb++) {
                u32 vh_[4], vl_[4];
                u32 va = v_off + c * 4352 + nb * 32;
                ldsm4t(vh_, sb + VH + va);
                ldsm4t(vl_, sb + VL + va);
                mma_bf16(o[2 * nb],     aph, vh_[0], vh_[1]);
                mma_bf16(o[2 * nb + 1], aph, vh_[2], vh_[3]);
                mma_bf16(o[2 * nb],     aph, vl_[0], vl_[1]);
                mma_bf16(o[2 * nb + 1], aph, vl_[2], vl_[3]);
                mma_bf16(o[2 * nb],     apl, vh_[0], vh_[1]);
                mma_bf16(o[2 * nb + 1], apl, vh_[2], vh_[3]);
            }
        }

        __syncthreads();            // all warps done reading V(j)
        load_V(j + 1);              // hides under next S
    }

    // ---- epilogue: O/l -> bf16 hi/lo ----
    const float inv0 = 1.0f / l0, inv1 = 1.0f / l1;
    const size_t obase = (size_t)b * AT_T * AT_C + (size_t)hd * AT_D;
    #pragma unroll
    for (int nf = 0; nf < 16; nf++) {
        int d = nf * 8 + 2 * (lane & 3);
        u32 h0, lo0, h1, lo1;
        pack2hl(o[nf][0] * inv0, o[nf][1] * inv0, h0, lo0);
        pack2hl(o[nf][2] * inv1, o[nf][3] * inv1, h1, lo1);
        size_t i0 = obase + (size_t)qrow0 * AT_C + d;
        size_t i1 = obase + (size_t)qrow1 * AT_C + d;
        *(u32*)(g_xoh + i0) = h0;  *(u32*)(g_xol + i0) = lo0;
        *(u32*)(g_xoh + i1) = h1;  *(u32*)(g_xol + i1) = lo1;
    }
}

// ---------------------------------------------------------------------------
// Launch: fused split -> merged QKV proj -> TC attention -> out proj
// ---------------------------------------------------------------------------
extern "C" void kernel_launch(void* const* d_in, const int* in_sizes, int n_in,
                              void* d_out, int out_size)
{
    const float* q   = (const float*)d_in[0];
    const float* k   = (const float*)d_in[1];
    const float* v   = (const float*)d_in[2];
    const float* ipw = (const float*)d_in[3];  // (3072, 2048)
    const float* ipb = (const float*)d_in[4];  // (3072,)
    const float* opw = (const float*)d_in[5];  // (2048, 2048)
    const float* opb = (const float*)d_in[6];  // (2048,)
    float* out = (float*)d_out;

    __nv_bfloat16 *qh, *ql, *kh, *kl, *vh, *vl, *wih, *wil, *woh, *wol;
    cudaGetSymbolAddress((void**)&qh, g_qh);   cudaGetSymbolAddress((void**)&ql, g_ql);
    cudaGetSymbolAddress((void**)&kh, g_kh);   cudaGetSymbolAddress((void**)&kl, g_kl);
    cudaGetSymbolAddress((void**)&vh, g_vh);   cudaGetSymbolAddress((void**)&vl, g_vl);
    cudaGetSymbolAddress((void**)&wih, g_wih); cudaGetSymbolAddress((void**)&wil, g_wil);
    cudaGetSymbolAddress((void**)&woh, g_woh); cudaGetSymbolAddress((void**)&wol, g_wol);

    const int attn_smem = 104448;  // (64+64+64) rows x 272 B x hi/lo
    cudaFuncSetAttribute(attn_tc_kernel, cudaFuncAttributeMaxDynamicSharedMemorySize, attn_smem);
    const int gemm_smem = 4 * STAGE_B;  // 98304
    cudaFuncSetAttribute(gemm_mma_proj, cudaFuncAttributeMaxDynamicSharedMemorySize, gemm_smem);
    cudaFuncSetAttribute(gemm_mma_out,  cudaFuncAttributeMaxDynamicSharedMemorySize, gemm_smem);

    dim3 blk(256);
    const int M_BLK = (AT_B * AT_T) / 128;  // 64

    // Fused prep: split inputs + weights into bf16 hi/lo (one launch)
    split_all_kernel<<<4096, 256>>>((const float4*)q, (const float4*)k, (const float4*)v,
                                    (const float4*)ipw, (const float4*)opw,
                                    (uint2*)qh, (uint2*)ql, (uint2*)kh, (uint2*)kl,
                                    (uint2*)vh, (uint2*)vl, (uint2*)wih, (uint2*)wil,
                                    (uint2*)woh, (uint2*)wol);

    // Merged Q+K+V projection (one launch, grid 24 x 64; Q pre-scaled to log2 domain)
    gemm_mma_proj<<<dim3(24, M_BLK), blk, gemm_smem>>>(ipb);

    // Tensor-core causal GQA flash attention (BM=64, occ 2, pipelined K/V)
    attn_tc_kernel<<<dim3(AT_B * AT_H, AT_T / 64), dim3(128), attn_smem>>>();

    // Output projection (fp32 out)
    gemm_mma_out<<<dim3(AT_C / 128, M_BLK), blk, gemm_smem>>>(opb, out);
}